// round 2
// baseline (speedup 1.0000x reference)
#include <cuda_runtime.h>

#define N 8192
#define THREADS 256
#define ROWS_PER_BLOCK 8
#define TILE 2048              // floats per smem tile (8 KB)
#define NTILES (N / TILE)      // 4
#define ITERS (TILE / (32 * 4))  // 16 float4 iters per lane per tile

__device__ float g_r[N];   // tanh(y), computed once

__global__ void tanh_kernel(const float* __restrict__ y)
{
    int i = blockIdx.x * blockDim.x + threadIdx.x;
    g_r[i] = tanhf(y[i]);
}

__global__ __launch_bounds__(THREADS, 8) void gemv_kernel(
    const float* __restrict__ x,
    const float* __restrict__ y,
    const float* __restrict__ W,
    float* __restrict__ out)
{
    __shared__ float r_s[TILE];  // 8 KB

    const int tid  = threadIdx.x;
    const int warp = tid >> 5;
    const int lane = tid & 31;
    const int row  = blockIdx.x * ROWS_PER_BLOCK + warp;

    const float4* __restrict__ Wrow =
        reinterpret_cast<const float4*>(W + (size_t)row * N);
    float4* rs4 = reinterpret_cast<float4*>(r_s);

    float a0 = 0.f, a1 = 0.f, a2 = 0.f, a3 = 0.f;

    #pragma unroll
    for (int t = 0; t < NTILES; t++) {
        // Stage this tile of r (L2-resident after tanh_kernel) into smem.
        const float4* rsrc = reinterpret_cast<const float4*>(g_r + t * TILE);
        #pragma unroll
        for (int i = tid; i < TILE / 4; i += THREADS)
            rs4[i] = __ldg(&rsrc[i]);
        __syncthreads();

        const float4* Wt = Wrow + t * (TILE / 4);
        #pragma unroll
        for (int i = 0; i < ITERS; i += 4) {
            float4 w0 = __ldcs(&Wt[(i + 0) * 32 + lane]);
            float4 w1 = __ldcs(&Wt[(i + 1) * 32 + lane]);
            float4 w2 = __ldcs(&Wt[(i + 2) * 32 + lane]);
            float4 w3 = __ldcs(&Wt[(i + 3) * 32 + lane]);
            float4 v0 = rs4[(i + 0) * 32 + lane];
            float4 v1 = rs4[(i + 1) * 32 + lane];
            float4 v2 = rs4[(i + 2) * 32 + lane];
            float4 v3 = rs4[(i + 3) * 32 + lane];
            a0 += w0.x * v0.x + w0.y * v0.y + w0.z * v0.z + w0.w * v0.w;
            a1 += w1.x * v1.x + w1.y * v1.y + w1.z * v1.z + w1.w * v1.w;
            a2 += w2.x * v2.x + w2.y * v2.y + w2.z * v2.z + w2.w * v2.w;
            a3 += w3.x * v3.x + w3.y * v3.y + w3.z * v3.z + w3.w * v3.w;
        }
        __syncthreads();  // protect tile before next overwrite
    }

    float acc = (a0 + a1) + (a2 + a3);

    #pragma unroll
    for (int off = 16; off > 0; off >>= 1)
        acc += __shfl_xor_sync(0xFFFFFFFFu, acc, off);

    if (lane == 0) {
        const float DT  = 1e-3f;
        const float TAU = 1e-2f;
        float yi = y[row];
        float dy = (-yi + acc + x[row]) / TAU;
        out[row] = yi + DT * dy;
    }
}

extern "C" void kernel_launch(void* const* d_in, const int* in_sizes, int n_in,
                              void* d_out, int out_size)
{
    const float* x = (const float*)d_in[0];
    const float* y = (const float*)d_in[1];
    const float* W = (const float*)d_in[2];
    float* out = (float*)d_out;

    tanh_kernel<<<N / THREADS, THREADS>>>(y);
    gemv_kernel<<<N / ROWS_PER_BLOCK, THREADS>>>(x, y, W, out);
}